// round 11
// baseline (speedup 1.0000x reference)
#include <cuda_runtime.h>
#include <cuda_bf16.h>
#include <cstdint>

// ---------------------------------------------------------------------------
// EBTAttention R8: gemm_v3 (reverted from v4 regression) + flash with
// register-resident Q and race-free pipeline.
// ---------------------------------------------------------------------------

#define BATCH 2
#define SEQ   2048
#define HID   2048
#define NH    16
#define HD    128
#define QKV_COLS 6144
#define ROWS  4096
#define NZ    32
#define GK    2048

typedef unsigned short u16;

static __device__ __align__(16) float g_qkv[(size_t)ROWS * QKV_COLS];
static __device__ __align__(16) u16 g_h_hi[(size_t)ROWS * HID];
static __device__ __align__(16) u16 g_h_lo[(size_t)ROWS * HID];
static __device__ __align__(16) u16 g_wqkv_hi[(size_t)QKV_COLS * HID];
static __device__ __align__(16) u16 g_wqkv_lo[(size_t)QKV_COLS * HID];
static __device__ __align__(16) u16 g_wo_hi[(size_t)HID * HID];
static __device__ __align__(16) u16 g_wo_lo[(size_t)HID * HID];
static __device__ __align__(16) u16 g_q_hi[(size_t)NZ * SEQ * HD];
static __device__ __align__(16) u16 g_q_lo[(size_t)NZ * SEQ * HD];
static __device__ __align__(16) u16 g_k_hi[(size_t)NZ * SEQ * HD];
static __device__ __align__(16) u16 g_k_lo[(size_t)NZ * SEQ * HD];
static __device__ __align__(16) u16 g_v_hi[(size_t)NZ * SEQ * HD];
static __device__ __align__(16) u16 g_v_lo[(size_t)NZ * SEQ * HD];
static __device__ __align__(16) u16 g_ao_hi[(size_t)ROWS * HID];
static __device__ __align__(16) u16 g_ao_lo[(size_t)ROWS * HID];

#define QSCALE 0.12751882456102142f   // (1/sqrt(128)) * log2(e)

__device__ __forceinline__ uint32_t smem_u32(const void* p) {
    uint32_t a;
    asm("{ .reg .u64 t; cvta.to.shared.u64 t, %1; cvt.u32.u64 %0, t; }" : "=r"(a) : "l"(p));
    return a;
}

#define LDSM_X4(r0, r1, r2, r3, addr) \
    asm volatile("ldmatrix.sync.aligned.m8n8.x4.shared.b16 {%0,%1,%2,%3}, [%4];" \
                 : "=r"(r0), "=r"(r1), "=r"(r2), "=r"(r3) : "r"(addr))
#define LDSM_X4_T(r0, r1, r2, r3, addr) \
    asm volatile("ldmatrix.sync.aligned.m8n8.x4.trans.shared.b16 {%0,%1,%2,%3}, [%4];" \
                 : "=r"(r0), "=r"(r1), "=r"(r2), "=r"(r3) : "r"(addr))

#define MMA16816(d, a, b0, b1) \
    asm volatile("mma.sync.aligned.m16n8k16.row.col.f32.bf16.bf16.f32 " \
                 "{%0,%1,%2,%3}, {%4,%5,%6,%7}, {%8,%9}, {%0,%1,%2,%3};" \
                 : "+f"((d)[0]), "+f"((d)[1]), "+f"((d)[2]), "+f"((d)[3]) \
                 : "r"((a)[0]), "r"((a)[1]), "r"((a)[2]), "r"((a)[3]), \
                   "r"(b0), "r"(b1))

#define CP_ASYNC16(s, g) \
    asm volatile("cp.async.ca.shared.global [%0], [%1], 16;" :: "r"(s), "l"(g))
#define CP_COMMIT() asm volatile("cp.async.commit_group;" ::: "memory")
#define CP_WAIT1()  asm volatile("cp.async.wait_group 1;" ::: "memory")
#define CP_WAIT0()  asm volatile("cp.async.wait_group 0;" ::: "memory")

__device__ __forceinline__ uint32_t packbf(__nv_bfloat16 a, __nv_bfloat16 b) {
    return ((uint32_t)__bfloat16_as_ushort(b) << 16) | __bfloat16_as_ushort(a);
}
__device__ __forceinline__ void split2(float x, float y, uint32_t& hi, uint32_t& lo) {
    __nv_bfloat16 hx = __float2bfloat16_rn(x);
    __nv_bfloat16 hy = __float2bfloat16_rn(y);
    hi = packbf(hx, hy);
    lo = packbf(__float2bfloat16_rn(x - __bfloat162float(hx)),
                __float2bfloat16_rn(y - __bfloat162float(hy)));
}

__global__ void __launch_bounds__(256) k_split(const float* __restrict__ src,
                                               u16* __restrict__ hi, u16* __restrict__ lo)
{
    size_t i = ((size_t)blockIdx.x * 256 + threadIdx.x) * 4;
    float4 v = *(const float4*)(src + i);
    uint32_t h0, l0, h1, l1;
    split2(v.x, v.y, h0, l0);
    split2(v.z, v.w, h1, l1);
    uint2 uh = {h0, h1}, ul = {l0, l1};
    *(uint2*)(hi + i) = uh;
    *(uint2*)(lo + i) = ul;
}

// ---------------------------------------------------------------------------
// GEMM v3 (R5 config — best measured): co-resident Ah/Al/Bh/Bl per 32-k chunk,
// 3-stage cp.async, XOR swizzle, 128x128 tile, 256 thr, 2 CTAs/SM.
// ---------------------------------------------------------------------------
#define GSTAGE 32768
#define GTILE  8192
#define GSMEM  98304

__device__ __forceinline__ void gemm_v3(
    const u16* __restrict__ Ah_, const u16* __restrict__ Al_,
    const u16* __restrict__ Bh_, const u16* __restrict__ Bl_,
    float* __restrict__ C, int ldc)
{
    extern __shared__ __align__(16) unsigned char gsm[];
    const uint32_t smb = smem_u32(gsm);

    const int tid = threadIdx.x, lane = tid & 31, wid = tid >> 5;
    const int wm = wid >> 1, wn = wid & 1;
    const int m0 = blockIdx.y * 128, n0 = blockIdx.x * 128;

    float acc[2][8][4] = {};

    const int r = tid >> 1;
    const int cp0 = (tid & 1) * 2;
    const uint32_t xs = (uint32_t)((r >> 1) & 3);
    const uint32_t st0 = (uint32_t)r * 64 + (((uint32_t)cp0 ^ xs) << 4);
    const uint32_t st1 = (uint32_t)r * 64 + (((uint32_t)(cp0 + 1) ^ xs) << 4);
    const size_t gA0 = (size_t)(m0 + r) * GK + cp0 * 8;
    const size_t gB0 = (size_t)(n0 + r) * GK + cp0 * 8;

#define G_LOAD(kt, buf) do { \
        const uint32_t sb_ = smb + (uint32_t)(buf) * GSTAGE; \
        const size_t ga_ = gA0 + (size_t)(kt) * 32; \
        const size_t gb_ = gB0 + (size_t)(kt) * 32; \
        CP_ASYNC16(sb_ + st0, Ah_ + ga_); \
        CP_ASYNC16(sb_ + st1, Ah_ + ga_ + 8); \
        CP_ASYNC16(sb_ + GTILE + st0, Al_ + ga_); \
        CP_ASYNC16(sb_ + GTILE + st1, Al_ + ga_ + 8); \
        CP_ASYNC16(sb_ + 2 * GTILE + st0, Bh_ + gb_); \
        CP_ASYNC16(sb_ + 2 * GTILE + st1, Bh_ + gb_ + 8); \
        CP_ASYNC16(sb_ + 3 * GTILE + st0, Bl_ + gb_); \
        CP_ASYNC16(sb_ + 3 * GTILE + st1, Bl_ + gb_ + 8); \
    } while (0)

    const int l15 = lane & 15;
    const int l7  = lane & 7;
    const uint32_t xrA = (uint32_t)((l15 >> 1) & 3);
    const uint32_t xrB = (uint32_t)((l7 >> 1) & 3);
    const uint32_t arow = (uint32_t)(wm * 32 + l15) * 64;
    const uint32_t brow = (uint32_t)(wn * 64 + ((lane >> 4) & 1) * 8 + l7) * 64;
    const uint32_t abit = (uint32_t)(lane >> 4);
    const uint32_t bbit = (uint32_t)((lane >> 3) & 1);
    uint32_t aswz[2], bswz[2];
#pragma unroll
    for (int ci = 0; ci < 2; ci++) {
        aswz[ci] = (((uint32_t)(2 * ci) + abit) ^ xrA) << 4;
        bswz[ci] = (((uint32_t)(2 * ci) + bbit) ^ xrB) << 4;
    }

    const int NCH = GK / 32;  // 64

    G_LOAD(0, 0); CP_COMMIT();
    G_LOAD(1, 1); CP_COMMIT();

    int buf = 0;
    for (int c = 0; c < NCH; c++) {
        CP_WAIT1();
        __syncthreads();

        if (c + 2 < NCH) {
            int nb = buf + 2; if (nb >= 3) nb -= 3;
            G_LOAD(c + 2, nb);
        }
        CP_COMMIT();

        const uint32_t sb = smb + (uint32_t)buf * GSTAGE;
#pragma unroll
        for (int ci = 0; ci < 2; ci++) {
            uint32_t ah[2][4], al[2][4];
#pragma unroll
            for (int mf = 0; mf < 2; mf++) {
                LDSM_X4(ah[mf][0], ah[mf][1], ah[mf][2], ah[mf][3],
                        sb + arow + mf * 1024 + aswz[ci]);
                LDSM_X4(al[mf][0], al[mf][1], al[mf][2], al[mf][3],
                        sb + GTILE + arow + mf * 1024 + aswz[ci]);
            }
#pragma unroll
            for (int p = 0; p < 4; p++) {
                uint32_t bh[4], bl[4];
                LDSM_X4(bh[0], bh[1], bh[2], bh[3],
                        sb + 2 * GTILE + brow + p * 1024 + bswz[ci]);
                LDSM_X4(bl[0], bl[1], bl[2], bl[3],
                        sb + 3 * GTILE + brow + p * 1024 + bswz[ci]);
#pragma unroll
                for (int mf = 0; mf < 2; mf++) {
                    MMA16816(acc[mf][2*p],   ah[mf], bh[0], bh[1]);
                    MMA16816(acc[mf][2*p],   ah[mf], bl[0], bl[1]);
                    MMA16816(acc[mf][2*p],   al[mf], bh[0], bh[1]);
                    MMA16816(acc[mf][2*p+1], ah[mf], bh[2], bh[3]);
                    MMA16816(acc[mf][2*p+1], ah[mf], bl[2], bl[3]);
                    MMA16816(acc[mf][2*p+1], al[mf], bh[2], bh[3]);
                }
            }
        }
        if (++buf == 3) buf = 0;
    }
#undef G_LOAD

    const int crow = m0 + wm * 32 + (lane >> 2);
    const int ccol = n0 + wn * 64 + (lane & 3) * 2;
#pragma unroll
    for (int mf = 0; mf < 2; mf++)
#pragma unroll
        for (int nf = 0; nf < 8; nf++) {
            float2 v0 = {acc[mf][nf][0], acc[mf][nf][1]};
            float2 v1 = {acc[mf][nf][2], acc[mf][nf][3]};
            *(float2*)(C + (size_t)(crow + mf * 16)     * ldc + ccol + nf * 8) = v0;
            *(float2*)(C + (size_t)(crow + mf * 16 + 8) * ldc + ccol + nf * 8) = v1;
        }
}

__global__ void __launch_bounds__(256, 2) k_qkv()
{
    gemm_v3(g_h_hi, g_h_lo, g_wqkv_hi, g_wqkv_lo, g_qkv, QKV_COLS);
}

__global__ void __launch_bounds__(256, 2) k_oproj(float* __restrict__ out)
{
    gemm_v3(g_ao_hi, g_ao_lo, g_wo_hi, g_wo_lo, out, HID);
}

// ---------------------------------------------------------------------------
// RoPE + split + repack q/k/v (q folded with scale*log2e).
// ---------------------------------------------------------------------------
__global__ void __launch_bounds__(256) k_rope_split(const float* __restrict__ cosp,
                                                    const float* __restrict__ sinp)
{
    const int d = threadIdx.x & 63;
    const int row = blockIdx.x * 4 + (threadIdx.x >> 6);
    const int head = blockIdx.y;
    const int s = row & (SEQ - 1);
    const int b = row >> 11;

    const float* p = g_qkv + (size_t)row * QKV_COLS + head * HD;
    float x1 = p[d];
    float x2 = p[d + 64];
    float y1, y2;
    if (head < 32) {
        float c1 = cosp[s * HD + d],      s1 = sinp[s * HD + d];
        float c2 = cosp[s * HD + d + 64], s2 = sinp[s * HD + d + 64];
        y1 = x1 * c1 - x2 * s1;
        y2 = x2 * c2 + x1 * s2;
    } else { y1 = x1; y2 = x2; }

    u16 *dh, *dl;
    int h;
    if (head < 16)      { h = head;      dh = g_q_hi; dl = g_q_lo; y1 *= QSCALE; y2 *= QSCALE; }
    else if (head < 32) { h = head - 16; dh = g_k_hi; dl = g_k_lo; }
    else                { h = head - 32; dh = g_v_hi; dl = g_v_lo; }

    const size_t base = ((size_t)(b * NH + h) * SEQ + s) * HD;
    __nv_bfloat16 h1 = __float2bfloat16_rn(y1);
    __nv_bfloat16 h2 = __float2bfloat16_rn(y2);
    dh[base + d]      = __bfloat16_as_ushort(h1);
    dh[base + d + 64] = __bfloat16_as_ushort(h2);
    dl[base + d]      = __bfloat16_as_ushort(__float2bfloat16_rn(y1 - __bfloat162float(h1)));
    dl[base + d + 64] = __bfloat16_as_ushort(__float2bfloat16_rn(y2 - __bfloat162float(h2)));
}

// ---------------------------------------------------------------------------
// Flash attention: Q register-resident, race-free double-buffered KV pipeline.
// ---------------------------------------------------------------------------
#define FSTR 272
#define QTILE 34816
#define KVT   17408
#define KVBUF 69632
#define FSMEM 208896

__global__ void __launch_bounds__(256, 1) k_flash()
{
    extern __shared__ __align__(16) unsigned char dsm[];
    const int tid = threadIdx.x, lane = tid & 31, w = tid >> 5;
    const int qb = blockIdx.x, z = blockIdx.y;
    const int b = z >> 4, h = z & 15;

    const uint32_t smQh = smem_u32(dsm);
    const uint32_t smQl = smQh + QTILE;
    const uint32_t smKV = smQh + 2 * QTILE;

    const size_t zbase = (size_t)z * SEQ * HD;
    const u16* gqh = g_q_hi + zbase + (size_t)qb * 128 * HD;
    const u16* gql = g_q_lo + zbase + (size_t)qb * 128 * HD;
    const u16* gkh = g_k_hi + zbase;
    const u16* gkl = g_k_lo + zbase;
    const u16* gvh = g_v_hi + zbase;
    const u16* gvl = g_v_lo + zbase;

    {
#pragma unroll
        for (int i = 0; i < 8; i++) {
            int ch = i * 256 + tid;
            int r = ch >> 4, q = ch & 15;
            CP_ASYNC16(smQh + r * FSTR + q * 16, gqh + r * HD + q * 8);
            CP_ASYNC16(smQl + r * FSTR + q * 16, gql + r * HD + q * 8);
        }
    }
#define LOAD_KV(t, buf) do { \
        uint32_t kb = smKV + (buf) * KVBUF; \
        const size_t rb = (size_t)(t) * 64; \
        _Pragma("unroll") \
        for (int i = 0; i < 4; i++) { \
            int ch = i * 256 + tid; \
            int r = ch >> 4, q = ch & 15; \
            uint32_t so = r * FSTR + q * 16; \
            size_t go = (rb + r) * HD + q * 8; \
            CP_ASYNC16(kb + so,            gkh + go); \
            CP_ASYNC16(kb + KVT + so,      gkl + go); \
            CP_ASYNC16(kb + 2 * KVT + so,  gvh + go); \
            CP_ASYNC16(kb + 3 * KVT + so,  gvl + go); \
        } \
    } while (0)

    LOAD_KV(0, 0);
    CP_COMMIT();

    const uint32_t a_off = (uint32_t)(w * 16 + (lane & 15)) * FSTR + ((lane >> 4) * 16);
    const uint32_t kb_off = (uint32_t)(((lane >> 4) & 1) * 8 + (lane & 7)) * FSTR
                          + (((lane >> 3) & 1) * 16);
    const uint32_t v_off = (uint32_t)(((lane >> 3) & 1) * 8 + (lane & 7)) * FSTR
                         + (((lane >> 4) & 1) * 16);

    CP_WAIT0();
    __syncthreads();
    uint32_t qh[8][4], ql[8][4];
#pragma unroll
    for (int c = 0; c < 8; c++) {
        LDSM_X4(qh[c][0], qh[c][1], qh[c][2], qh[c][3], smQh + a_off + c * 32);
        LDSM_X4(ql[c][0], ql[c][1], ql[c][2], ql[c][3], smQl + a_off + c * 32);
    }

    float o[16][4] = {};
    float m0 = -1e30f, m1 = -1e30f, l0 = 0.0f, l1 = 0.0f;

    for (int t = 0; t < 32; t++) {
        if (t + 1 < 32) LOAD_KV(t + 1, (t + 1) & 1);
        CP_COMMIT();

        const uint32_t kb = smKV + (t & 1) * KVBUF;
        const uint32_t sKh = kb + kb_off;
        const uint32_t sKl = kb + KVT + kb_off;
        const uint32_t sVh = kb + 2 * KVT + v_off;
        const uint32_t sVl = kb + 3 * KVT + v_off;

        float sf[8][4] = {};
#pragma unroll
        for (int c = 0; c < 8; c++) {
#pragma unroll
            for (int p = 0; p < 4; p++) {
                uint32_t kh[4], kl[4];
                LDSM_X4(kh[0], kh[1], kh[2], kh[3], sKh + p * 16 * FSTR + c * 32);
                LDSM_X4(kl[0], kl[1], kl[2], kl[3], sKl + p * 16 * FSTR + c * 32);
                MMA16816(sf[2*p],   qh[c], kh[0], kh[1]);
                MMA16816(sf[2*p],   qh[c], kl[0], kl[1]);
                MMA16816(sf[2*p],   ql[c], kh[0], kh[1]);
                MMA16816(sf[2*p+1], qh[c], kh[2], kh[3]);
                MMA16816(sf[2*p+1], qh[c], kl[2], kl[3]);
                MMA16816(sf[2*p+1], ql[c], kh[2], kh[3]);
            }
        }

        float tm0 = -1e30f, tm1 = -1e30f;
#pragma unroll
        for (int e = 0; e < 8; e++) {
            tm0 = fmaxf(tm0, fmaxf(sf[e][0], sf[e][1]));
            tm1 = fmaxf(tm1, fmaxf(sf[e][2], sf[e][3]));
        }
        tm0 = fmaxf(tm0, __shfl_xor_sync(0xffffffffu, tm0, 1));
        tm0 = fmaxf(tm0, __shfl_xor_sync(0xffffffffu, tm0, 2));
        tm1 = fmaxf(tm1, __shfl_xor_sync(0xffffffffu, tm1, 1));
        tm1 = fmaxf(tm1, __shfl_xor_sync(0xffffffffu, tm1, 2));
        const float m0n = fmaxf(m0, tm0), m1n = fmaxf(m1, tm1);
        const float c0 = exp2f(m0 - m0n), c1 = exp2f(m1 - m1n);
        float ts0 = 0.0f, ts1 = 0.0f;
#pragma unroll
        for (int e = 0; e < 8; e++) {
            sf[e][0] = exp2f(sf[e][0] - m0n);
            sf[e][1] = exp2f(sf[e][1] - m0n);
            sf[e][2] = exp2f(sf[e][2] - m1n);
            sf[e][3] = exp2f(sf[e][3] - m1n);
            ts0 += sf[e][0] + sf[e][1];
            ts1 += sf[e][2] + sf[e][3];
        }
        ts0 += __shfl_xor_sync(0xffffffffu, ts0, 1);
        ts0 += __shfl_xor_sync(0xffffffffu, ts0, 2);
        ts1 += __shfl_xor_sync(0xffffffffu, ts1, 1);
        ts1 += __shfl_xor_sync(0xffffffffu, ts1, 2);
        l0 = l0 * c0 + ts0;
        l1 = l1 * c1 + ts1;
        m0 = m0n; m1 = m1n;
#pragma unroll
        for (int f = 0; f < 16; f++) {
            o[f][0] *= c0; o[f][1] *= c0;
            o[f][2] *= c1; o[f][3] *= c1;
        }

#pragma unroll
        for (int j = 0; j < 4; j++) {
            uint32_t ah[4], al[4];
            split2(sf[2*j][0],   sf[2*j][1],   ah[0], al[0]);
            split2(sf[2*j][2],   sf[2*j][3],   ah[1], al[1]);
            split2(sf[2*j+1][0], sf[2*j+1][1], ah[2], al[2]);
            split2(sf[2*j+1][2], sf[2*j+1][3], ah[3], al[3]);
#pragma unroll
            for (int f = 0; f < 8; f++) {
                uint32_t vh[4], vl[4];
                LDSM_X4_T(vh[0], vh[1], vh[2], vh[3], sVh + j * 16 * FSTR + f * 32);
                LDSM_X4_T(vl[0], vl[1], vl[2], vl[3], sVl + j * 16 * FSTR + f * 32);
                MMA16816(o[2*f],   ah, vh[0], vh[1]);
                MMA16816(o[2*f],   ah, vl[0], vl[1]);
                MMA16816(o[2*f],   al, vh[0], vh[1]);
                MMA16816(o[2*f+1], ah, vh[2], vh[3]);
                MMA16816(o[2*f+1], ah, vl[2], vl[3]);
                MMA16816(o[2*f+1], al, vh[2], vh[3]);
            }
        }

        CP_WAIT0();
        __syncthreads();
    }
#undef LOAD_KV

    const float inv0 = 1.0f / l0, inv1 = 1.0f / l1;
    const size_t row0 = (size_t)(b * SEQ + qb * 128 + w * 16 + (lane >> 2));
    const size_t colb = (size_t)h * HD + (lane & 3) * 2;
#pragma unroll
    for (int f = 0; f < 16; f++) {
        uint32_t h01, l01, h23, l23;
        split2(o[f][0] * inv0, o[f][1] * inv0, h01, l01);
        split2(o[f][2] * inv1, o[f][3] * inv1, h23, l23);
        size_t i0 = row0 * HID + colb + f * 8;
        size_t i1 = i0 + (size_t)8 * HID;
        *(uint32_t*)(g_ao_hi + i0) = h01;
        *(uint32_t*)(g_ao_lo + i0) = l01;
        *(uint32_t*)(g_ao_hi + i1) = h23;
        *(uint32_t*)(g_ao_lo + i1) = l23;
    }
}

// ---------------------------------------------------------------------------
// Launch
// ---------------------------------------------------------------------------
extern "C" void kernel_launch(void* const* d_in, const int* in_sizes, int n_in,
                              void* d_out, int out_size)
{
    const float* hidden = (const float*)d_in[0];
    const float* cosp   = (const float*)d_in[1];
    const float* sinp   = (const float*)d_in[2];
    const float* wqkv   = (const float*)d_in[3];
    const float* wo     = (const float*)d_in[4];
    float* out = (float*)d_out;

    cudaFuncSetAttribute(k_flash, cudaFuncAttributeMaxDynamicSharedMemorySize, FSMEM);
    cudaFuncSetAttribute(k_qkv,   cudaFuncAttributeMaxDynamicSharedMemorySize, GSMEM);
    cudaFuncSetAttribute(k_oproj, cudaFuncAttributeMaxDynamicSharedMemorySize, GSMEM);

    u16 *hh, *hl, *wh, *wl, *oh, *ol;
    cudaGetSymbolAddress((void**)&hh, g_h_hi);
    cudaGetSymbolAddress((void**)&hl, g_h_lo);
    cudaGetSymbolAddress((void**)&wh, g_wqkv_hi);
    cudaGetSymbolAddress((void**)&wl, g_wqkv_lo);
    cudaGetSymbolAddress((void**)&oh, g_wo_hi);
    cudaGetSymbolAddress((void**)&ol, g_wo_lo);

    k_split<<<(ROWS * HID) / 1024, 256>>>(hidden, hh, hl);
    k_split<<<(QKV_COLS * HID) / 1024, 256>>>(wqkv, wh, wl);
    k_split<<<(HID * HID) / 1024, 256>>>(wo, oh, ol);

    k_qkv<<<dim3(QKV_COLS / 128, ROWS / 128), 256, GSMEM>>>();
    k_rope_split<<<dim3(1024, 48), 256>>>(cosp, sinp);
    k_flash<<<dim3(16, 32), 256, FSMEM>>>();
    k_oproj<<<dim3(HID / 128, ROWS / 128), 256, GSMEM>>>(out);
}

// round 12
// speedup vs baseline: 1.5191x; 1.5191x over previous
#include <cuda_runtime.h>
#include <cuda_bf16.h>
#include <cstdint>

// ---------------------------------------------------------------------------
// EBTAttention R11: exact R5 configuration restored (best measured: 1926us).
// gemm_v3 co-resident bf16x3 + R5 flash (smem Q, double-buffered KV).
// ---------------------------------------------------------------------------

#define BATCH 2
#define SEQ   2048
#define HID   2048
#define NH    16
#define HD    128
#define QKV_COLS 6144
#define ROWS  4096
#define NZ    32
#define GK    2048

typedef unsigned short u16;

static __device__ __align__(16) float g_qkv[(size_t)ROWS * QKV_COLS];
static __device__ __align__(16) u16 g_h_hi[(size_t)ROWS * HID];
static __device__ __align__(16) u16 g_h_lo[(size_t)ROWS * HID];
static __device__ __align__(16) u16 g_wqkv_hi[(size_t)QKV_COLS * HID];
static __device__ __align__(16) u16 g_wqkv_lo[(size_t)QKV_COLS * HID];
static __device__ __align__(16) u16 g_wo_hi[(size_t)HID * HID];
static __device__ __align__(16) u16 g_wo_lo[(size_t)HID * HID];
static __device__ __align__(16) u16 g_q_hi[(size_t)NZ * SEQ * HD];
static __device__ __align__(16) u16 g_q_lo[(size_t)NZ * SEQ * HD];
static __device__ __align__(16) u16 g_k_hi[(size_t)NZ * SEQ * HD];
static __device__ __align__(16) u16 g_k_lo[(size_t)NZ * SEQ * HD];
static __device__ __align__(16) u16 g_v_hi[(size_t)NZ * SEQ * HD];
static __device__ __align__(16) u16 g_v_lo[(size_t)NZ * SEQ * HD];
static __device__ __align__(16) u16 g_ao_hi[(size_t)ROWS * HID];
static __device__ __align__(16) u16 g_ao_lo[(size_t)ROWS * HID];

#define QSCALE 0.12751882456102142f   // (1/sqrt(128)) * log2(e)

__device__ __forceinline__ uint32_t smem_u32(const void* p) {
    uint32_t a;
    asm("{ .reg .u64 t; cvta.to.shared.u64 t, %1; cvt.u32.u64 %0, t; }" : "=r"(a) : "l"(p));
    return a;
}

#define LDSM_X4(r0, r1, r2, r3, addr) \
    asm volatile("ldmatrix.sync.aligned.m8n8.x4.shared.b16 {%0,%1,%2,%3}, [%4];" \
                 : "=r"(r0), "=r"(r1), "=r"(r2), "=r"(r3) : "r"(addr))
#define LDSM_X4_T(r0, r1, r2, r3, addr) \
    asm volatile("ldmatrix.sync.aligned.m8n8.x4.trans.shared.b16 {%0,%1,%2,%3}, [%4];" \
                 : "=r"(r0), "=r"(r1), "=r"(r2), "=r"(r3) : "r"(addr))

#define MMA16816(d, a, b0, b1) \
    asm volatile("mma.sync.aligned.m16n8k16.row.col.f32.bf16.bf16.f32 " \
                 "{%0,%1,%2,%3}, {%4,%5,%6,%7}, {%8,%9}, {%0,%1,%2,%3};" \
                 : "+f"((d)[0]), "+f"((d)[1]), "+f"((d)[2]), "+f"((d)[3]) \
                 : "r"((a)[0]), "r"((a)[1]), "r"((a)[2]), "r"((a)[3]), \
                   "r"(b0), "r"(b1))

#define CP_ASYNC16(s, g) \
    asm volatile("cp.async.ca.shared.global [%0], [%1], 16;" :: "r"(s), "l"(g))
#define CP_COMMIT() asm volatile("cp.async.commit_group;" ::: "memory")
#define CP_WAIT1()  asm volatile("cp.async.wait_group 1;" ::: "memory")
#define CP_WAIT0()  asm volatile("cp.async.wait_group 0;" ::: "memory")

__device__ __forceinline__ uint32_t packbf(__nv_bfloat16 a, __nv_bfloat16 b) {
    return ((uint32_t)__bfloat16_as_ushort(b) << 16) | __bfloat16_as_ushort(a);
}
__device__ __forceinline__ void split2(float x, float y, uint32_t& hi, uint32_t& lo) {
    __nv_bfloat16 hx = __float2bfloat16_rn(x);
    __nv_bfloat16 hy = __float2bfloat16_rn(y);
    hi = packbf(hx, hy);
    lo = packbf(__float2bfloat16_rn(x - __bfloat162float(hx)),
                __float2bfloat16_rn(y - __bfloat162float(hy)));
}

__global__ void __launch_bounds__(256) k_split(const float* __restrict__ src,
                                               u16* __restrict__ hi, u16* __restrict__ lo)
{
    size_t i = ((size_t)blockIdx.x * 256 + threadIdx.x) * 4;
    float4 v = *(const float4*)(src + i);
    uint32_t h0, l0, h1, l1;
    split2(v.x, v.y, h0, l0);
    split2(v.z, v.w, h1, l1);
    uint2 uh = {h0, h1}, ul = {l0, l1};
    *(uint2*)(hi + i) = uh;
    *(uint2*)(lo + i) = ul;
}

// ---------------------------------------------------------------------------
// GEMM v3: co-resident Ah/Al/Bh/Bl per 32-k chunk, 3-stage cp.async pipeline,
// XOR-swizzled smem, 1 sync/stage. Tile 128x128, 256 thr, 2 CTAs/SM.
// ---------------------------------------------------------------------------
#define GSTAGE 32768
#define GTILE  8192
#define GSMEM  98304

__device__ __forceinline__ void gemm_v3(
    const u16* __restrict__ Ah_, const u16* __restrict__ Al_,
    const u16* __restrict__ Bh_, const u16* __restrict__ Bl_,
    float* __restrict__ C, int ldc)
{
    extern __shared__ __align__(16) unsigned char gsm[];
    const uint32_t smb = smem_u32(gsm);

    const int tid = threadIdx.x, lane = tid & 31, wid = tid >> 5;
    const int wm = wid >> 1, wn = wid & 1;
    const int m0 = blockIdx.y * 128, n0 = blockIdx.x * 128;

    float acc[2][8][4] = {};

    const int r = tid >> 1;
    const int cp0 = (tid & 1) * 2;
    const uint32_t xs = (uint32_t)((r >> 1) & 3);
    const uint32_t st0 = (uint32_t)r * 64 + (((uint32_t)cp0 ^ xs) << 4);
    const uint32_t st1 = (uint32_t)r * 64 + (((uint32_t)(cp0 + 1) ^ xs) << 4);
    const size_t gA0 = (size_t)(m0 + r) * GK + cp0 * 8;
    const size_t gB0 = (size_t)(n0 + r) * GK + cp0 * 8;

#define G_LOAD(kt, buf) do { \
        const uint32_t sb_ = smb + (uint32_t)(buf) * GSTAGE; \
        const size_t ga_ = gA0 + (size_t)(kt) * 32; \
        const size_t gb_ = gB0 + (size_t)(kt) * 32; \
        CP_ASYNC16(sb_ + st0, Ah_ + ga_); \
        CP_ASYNC16(sb_ + st1, Ah_ + ga_ + 8); \
        CP_ASYNC16(sb_ + GTILE + st0, Al_ + ga_); \
        CP_ASYNC16(sb_ + GTILE + st1, Al_ + ga_ + 8); \
        CP_ASYNC16(sb_ + 2 * GTILE + st0, Bh_ + gb_); \
        CP_ASYNC16(sb_ + 2 * GTILE + st1, Bh_ + gb_ + 8); \
        CP_ASYNC16(sb_ + 3 * GTILE + st0, Bl_ + gb_); \
        CP_ASYNC16(sb_ + 3 * GTILE + st1, Bl_ + gb_ + 8); \
    } while (0)

    const int l15 = lane & 15;
    const int l7  = lane & 7;
    const uint32_t xrA = (uint32_t)((l15 >> 1) & 3);
    const uint32_t xrB = (uint32_t)((l7 >> 1) & 3);
    const uint32_t arow = (uint32_t)(wm * 32 + l15) * 64;
    const uint32_t brow = (uint32_t)(wn * 64 + ((lane >> 4) & 1) * 8 + l7) * 64;
    const uint32_t abit = (uint32_t)(lane >> 4);
    const uint32_t bbit = (uint32_t)((lane >> 3) & 1);
    uint32_t aswz[2], bswz[2];
#pragma unroll
    for (int ci = 0; ci < 2; ci++) {
        aswz[ci] = (((uint32_t)(2 * ci) + abit) ^ xrA) << 4;
        bswz[ci] = (((uint32_t)(2 * ci) + bbit) ^ xrB) << 4;
    }

    const int NCH = GK / 32;  // 64

    G_LOAD(0, 0); CP_COMMIT();
    G_LOAD(1, 1); CP_COMMIT();

    int buf = 0;
    for (int c = 0; c < NCH; c++) {
        CP_WAIT1();
        __syncthreads();

        if (c + 2 < NCH) {
            int nb = buf + 2; if (nb >= 3) nb -= 3;
            G_LOAD(c + 2, nb);
        }
        CP_COMMIT();

        const uint32_t sb = smb + (uint32_t)buf * GSTAGE;
#pragma unroll
        for (int ci = 0; ci < 2; ci++) {
            uint32_t ah[2][4], al[2][4];
#pragma unroll
            for (int mf = 0; mf < 2; mf++) {
                LDSM_X4(ah[mf][0], ah[mf][1], ah[mf][2], ah[mf][3],
                        sb + arow + mf * 1024 + aswz[ci]);
                LDSM_X4(al[mf][0], al[mf][1], al[mf][2], al[mf][3],
                        sb + GTILE + arow + mf * 1024 + aswz[ci]);
            }
#pragma unroll
            for (int p = 0; p < 4; p++) {
                uint32_t bh[4], bl[4];
                LDSM_X4(bh[0], bh[1], bh[2], bh[3],
                        sb + 2 * GTILE + brow + p * 1024 + bswz[ci]);
                LDSM_X4(bl[0], bl[1], bl[2], bl[3],
                        sb + 3 * GTILE + brow + p * 1024 + bswz[ci]);
#pragma unroll
                for (int mf = 0; mf < 2; mf++) {
                    MMA16816(acc[mf][2*p],   ah[mf], bh[0], bh[1]);
                    MMA16816(acc[mf][2*p],   ah[mf], bl[0], bl[1]);
                    MMA16816(acc[mf][2*p],   al[mf], bh[0], bh[1]);
                    MMA16816(acc[mf][2*p+1], ah[mf], bh[2], bh[3]);
                    MMA16816(acc[mf][2*p+1], ah[mf], bl[2], bl[3]);
                    MMA16816(acc[mf][2*p+1], al[mf], bh[2], bh[3]);
                }
            }
        }
        if (++buf == 3) buf = 0;
    }
#undef G_LOAD

    const int crow = m0 + wm * 32 + (lane >> 2);
    const int ccol = n0 + wn * 64 + (lane & 3) * 2;
#pragma unroll
    for (int mf = 0; mf < 2; mf++)
#pragma unroll
        for (int nf = 0; nf < 8; nf++) {
            float2 v0 = {acc[mf][nf][0], acc[mf][nf][1]};
            float2 v1 = {acc[mf][nf][2], acc[mf][nf][3]};
            *(float2*)(C + (size_t)(crow + mf * 16)     * ldc + ccol + nf * 8) = v0;
            *(float2*)(C + (size_t)(crow + mf * 16 + 8) * ldc + ccol + nf * 8) = v1;
        }
}

__global__ void __launch_bounds__(256, 2) k_qkv()
{
    gemm_v3(g_h_hi, g_h_lo, g_wqkv_hi, g_wqkv_lo, g_qkv, QKV_COLS);
}

__global__ void __launch_bounds__(256, 2) k_oproj(float* __restrict__ out)
{
    gemm_v3(g_ao_hi, g_ao_lo, g_wo_hi, g_wo_lo, out, HID);
}

// ---------------------------------------------------------------------------
// RoPE + split + repack q/k/v (q folded with scale*log2e).
// ---------------------------------------------------------------------------
__global__ void __launch_bounds__(256) k_rope_split(const float* __restrict__ cosp,
                                                    const float* __restrict__ sinp)
{
    const int d = threadIdx.x & 63;
    const int row = blockIdx.x * 4 + (threadIdx.x >> 6);
    const int head = blockIdx.y;
    const int s = row & (SEQ - 1);
    const int b = row >> 11;

    const float* p = g_qkv + (size_t)row * QKV_COLS + head * HD;
    float x1 = p[d];
    float x2 = p[d + 64];
    float y1, y2;
    if (head < 32) {
        float c1 = cosp[s * HD + d],      s1 = sinp[s * HD + d];
        float c2 = cosp[s * HD + d + 64], s2 = sinp[s * HD + d + 64];
        y1 = x1 * c1 - x2 * s1;
        y2 = x2 * c2 + x1 * s2;
    } else { y1 = x1; y2 = x2; }

    u16 *dh, *dl;
    int h;
    if (head < 16)      { h = head;      dh = g_q_hi; dl = g_q_lo; y1 *= QSCALE; y2 *= QSCALE; }
    else if (head < 32) { h = head - 16; dh = g_k_hi; dl = g_k_lo; }
    else                { h = head - 32; dh = g_v_hi; dl = g_v_lo; }

    const size_t base = ((size_t)(b * NH + h) * SEQ + s) * HD;
    __nv_bfloat16 h1 = __float2bfloat16_rn(y1);
    __nv_bfloat16 h2 = __float2bfloat16_rn(y2);
    dh[base + d]      = __bfloat16_as_ushort(h1);
    dh[base + d + 64] = __bfloat16_as_ushort(h2);
    dl[base + d]      = __bfloat16_as_ushort(__float2bfloat16_rn(y1 - __bfloat162float(h1)));
    dl[base + d + 64] = __bfloat16_as_ushort(__float2bfloat16_rn(y2 - __bfloat162float(h2)));
}

// ---------------------------------------------------------------------------
// Flash attention (R5 version): smem Q, double-buffered KV via cp.async.
// ---------------------------------------------------------------------------
#define FSTR 272
#define QTILE 34816
#define KVT   17408
#define KVBUF 69632
#define FSMEM 208896

__global__ void __launch_bounds__(256, 1) k_flash()
{
    extern __shared__ __align__(16) unsigned char dsm[];
    const int tid = threadIdx.x, lane = tid & 31, w = tid >> 5;
    const int qb = blockIdx.x, z = blockIdx.y;
    const int b = z >> 4, h = z & 15;

    const uint32_t smQh = smem_u32(dsm);
    const uint32_t smQl = smQh + QTILE;
    const uint32_t smKV = smQh + 2 * QTILE;

    const size_t zbase = (size_t)z * SEQ * HD;
    const u16* gqh = g_q_hi + zbase + (size_t)qb * 128 * HD;
    const u16* gql = g_q_lo + zbase + (size_t)qb * 128 * HD;
    const u16* gkh = g_k_hi + zbase;
    const u16* gkl = g_k_lo + zbase;
    const u16* gvh = g_v_hi + zbase;
    const u16* gvl = g_v_lo + zbase;

    {
#pragma unroll
        for (int i = 0; i < 8; i++) {
            int ch = i * 256 + tid;
            int r = ch >> 4, q = ch & 15;
            CP_ASYNC16(smQh + r * FSTR + q * 16, gqh + r * HD + q * 8);
            CP_ASYNC16(smQl + r * FSTR + q * 16, gql + r * HD + q * 8);
        }
    }
#define LOAD_KV(t, buf) do { \
        uint32_t kb = smKV + (buf) * KVBUF; \
        const size_t rb = (size_t)(t) * 64; \
        _Pragma("unroll") \
        for (int i = 0; i < 4; i++) { \
            int ch = i * 256 + tid; \
            int r = ch >> 4, q = ch & 15; \
            uint32_t so = r * FSTR + q * 16; \
            size_t go = (rb + r) * HD + q * 8; \
            CP_ASYNC16(kb + so,            gkh + go); \
            CP_ASYNC16(kb + KVT + so,      gkl + go); \
            CP_ASYNC16(kb + 2 * KVT + so,  gvh + go); \
            CP_ASYNC16(kb + 3 * KVT + so,  gvl + go); \
        } \
    } while (0)

    LOAD_KV(0, 0);
    CP_COMMIT();

    const uint32_t a_off = (uint32_t)(w * 16 + (lane & 15)) * FSTR + ((lane >> 4) * 16);
    const uint32_t kb_off = (uint32_t)(((lane >> 4) & 1) * 8 + (lane & 7)) * FSTR
                          + (((lane >> 3) & 1) * 16);
    const uint32_t v_off = (uint32_t)(((lane >> 3) & 1) * 8 + (lane & 7)) * FSTR
                         + (((lane >> 4) & 1) * 16);

    float o[16][4] = {};
    float m0 = -1e30f, m1 = -1e30f, l0 = 0.0f, l1 = 0.0f;

    for (int t = 0; t < 32; t++) {
        if (t + 1 < 32) LOAD_KV(t + 1, (t + 1) & 1);
        CP_COMMIT();
        if (t + 1 < 32) { CP_WAIT1(); } else { CP_WAIT0(); }
        __syncthreads();

        const uint32_t kb = smKV + (t & 1) * KVBUF;
        const uint32_t sKh = kb + kb_off;
        const uint32_t sKl = kb + KVT + kb_off;
        const uint32_t sVh = kb + 2 * KVT + v_off;
        const uint32_t sVl = kb + 3 * KVT + v_off;
        const uint32_t sQh = smQh + a_off;
        const uint32_t sQl = smQl + a_off;

        float sf[8][4] = {};
#pragma unroll
        for (int c = 0; c < 8; c++) {
            uint32_t qh[4], ql[4];
            LDSM_X4(qh[0], qh[1], qh[2], qh[3], sQh + c * 32);
            LDSM_X4(ql[0], ql[1], ql[2], ql[3], sQl + c * 32);
#pragma unroll
            for (int p = 0; p < 4; p++) {
                uint32_t kh[4], kl[4];
                LDSM_X4(kh[0], kh[1], kh[2], kh[3], sKh + p * 16 * FSTR + c * 32);
                LDSM_X4(kl[0], kl[1], kl[2], kl[3], sKl + p * 16 * FSTR + c * 32);
                MMA16816(sf[2*p],   qh, kh[0], kh[1]);
                MMA16816(sf[2*p],   qh, kl[0], kl[1]);
                MMA16816(sf[2*p],   ql, kh[0], kh[1]);
                MMA16816(sf[2*p+1], qh, kh[2], kh[3]);
                MMA16816(sf[2*p+1], qh, kl[2], kl[3]);
                MMA16816(sf[2*p+1], ql, kh[2], kh[3]);
            }
        }

        float tm0 = -1e30f, tm1 = -1e30f;
#pragma unroll
        for (int e = 0; e < 8; e++) {
            tm0 = fmaxf(tm0, fmaxf(sf[e][0], sf[e][1]));
            tm1 = fmaxf(tm1, fmaxf(sf[e][2], sf[e][3]));
        }
        tm0 = fmaxf(tm0, __shfl_xor_sync(0xffffffffu, tm0, 1));
        tm0 = fmaxf(tm0, __shfl_xor_sync(0xffffffffu, tm0, 2));
        tm1 = fmaxf(tm1, __shfl_xor_sync(0xffffffffu, tm1, 1));
        tm1 = fmaxf(tm1, __shfl_xor_sync(0xffffffffu, tm1, 2));
        const float m0n = fmaxf(m0, tm0), m1n = fmaxf(m1, tm1);
        const float c0 = exp2f(m0 - m0n), c1 = exp2f(m1 - m1n);
        float ts0 = 0.0f, ts1 = 0.0f;
#pragma unroll
        for (int e = 0; e < 8; e++) {
            sf[e][0] = exp2f(sf[e][0] - m0n);
            sf[e][1] = exp2f(sf[e][1] - m0n);
            sf[e][2] = exp2f(sf[e][2] - m1n);
            sf[e][3] = exp2f(sf[e][3] - m1n);
            ts0 += sf[e][0] + sf[e][1];
            ts1 += sf[e][2] + sf[e][3];
        }
        ts0 += __shfl_xor_sync(0xffffffffu, ts0, 1);
        ts0 += __shfl_xor_sync(0xffffffffu, ts0, 2);
        ts1 += __shfl_xor_sync(0xffffffffu, ts1, 1);
        ts1 += __shfl_xor_sync(0xffffffffu, ts1, 2);
        l0 = l0 * c0 + ts0;
        l1 = l1 * c1 + ts1;
        m0 = m0n; m1 = m1n;
#pragma unroll
        for (int f = 0; f < 16; f++) {
            o[f][0] *= c0; o[f][1] *= c0;
            o[f][2] *= c1; o[f][3] *= c1;
        }

#pragma unroll
        for (int j = 0; j < 4; j++) {
            uint32_t ah[4], al[4];
            split2(sf[2*j][0],   sf[2*j][1],   ah[0], al[0]);
            split2(sf[2*j][2],   sf[2*j][3],   ah[1], al[1]);
            split2(sf[2*j+1][0], sf[2*j+1][1], ah[2], al[2]);
            split2(sf[2*j+1][2], sf[2*j+1][3], ah[3], al[3]);
#pragma unroll
            for (int f = 0; f < 8; f++) {
                uint32_t vh[4], vl[4];
                LDSM_X4_T(vh[0], vh[1], vh[2], vh[3], sVh + j * 16 * FSTR + f * 32);
                LDSM_X4_T(vl[0], vl[1], vl[2], vl[3], sVl + j * 16 * FSTR + f * 32);
                MMA16816(o[2*f],   ah, vh[0], vh[1]);
                MMA16816(o[2*f],   ah, vl[0], vl[1]);
                MMA16816(o[2*f],   al, vh[0], vh[1]);
                MMA16816(o[2*f+1], ah, vh[2], vh[3]);
                MMA16816(o[2*f+1], ah, vl[2], vl[3]);
                MMA16816(o[2*f+1], al, vh[2], vh[3]);
            }
        }
        __syncthreads();
    }
#undef LOAD_KV

    const float inv0 = 1.0f / l0, inv1 = 1.0f / l1;
    const size_t row0 = (size_t)(b * SEQ + qb * 128 + w * 16 + (lane >> 2));
    const size_t colb = (size_t)h * HD + (lane & 3) * 2;
#pragma unroll
    for (int f = 0; f < 16; f++) {
        uint32_t h01, l01, h23, l23;
        split2(o[f][0] * inv0, o[f][1] * inv0, h01, l01);
        split2(o[f][2] * inv1, o[f][3] * inv1, h23, l23);
        size_t i0 = row0 * HID + colb + f * 8;
        size_t i1 = i0 + (size_t)8 * HID;
        *(uint32_t*)(g_ao_hi + i0) = h01;
        *(uint32_t*)(g_ao_lo + i0) = l01;
        *(uint32_t*)(g_ao_hi + i1) = h23;
        *(uint32_t*)(g_ao_lo + i1) = l23;
    }
}

// ---------------------------------------------------------------------------
// Launch
// ---------------------------------------------------------------------------
extern "C" void kernel_launch(void* const* d_in, const int* in_sizes, int n_in,
                              void* d_out, int out_size)
{
    const float* hidden = (const float*)d_in[0];
    const float* cosp   = (const float*)d_in[1];
    const float* sinp   = (const float*)d_in[2];
    const float* wqkv   = (const float*)d_in[3];
    const float* wo     = (const float*)d_in[4];
    float* out = (float*)d_out;

    cudaFuncSetAttribute(k_flash, cudaFuncAttributeMaxDynamicSharedMemorySize, FSMEM);
    cudaFuncSetAttribute(k_qkv,   cudaFuncAttributeMaxDynamicSharedMemorySize, GSMEM);
    cudaFuncSetAttribute(k_oproj, cudaFuncAttributeMaxDynamicSharedMemorySize, GSMEM);

    u16 *hh, *hl, *wh, *wl, *oh, *ol;
    cudaGetSymbolAddress((void**)&hh, g_h_hi);
    cudaGetSymbolAddress((void**)&hl, g_h_lo);
    cudaGetSymbolAddress((void**)&wh, g_wqkv_hi);
    cudaGetSymbolAddress((void**)&wl, g_wqkv_lo);
    cudaGetSymbolAddress((void**)&oh, g_wo_hi);
    cudaGetSymbolAddress((void**)&ol, g_wo_lo);

    k_split<<<(ROWS * HID) / 1024, 256>>>(hidden, hh, hl);
    k_split<<<(QKV_COLS * HID) / 1024, 256>>>(wqkv, wh, wl);
    k_split<<<(HID * HID) / 1024, 256>>>(wo, oh, ol);

    k_qkv<<<dim3(QKV_COLS / 128, ROWS / 128), 256, GSMEM>>>();
    k_rope_split<<<dim3(1024, 48), 256>>>(cosp, sinp);
    k_flash<<<dim3(16, 32), 256, FSMEM>>>();
    k_oproj<<<dim3(HID / 128, ROWS / 128), 256, GSMEM>>>(out);
}